// round 1
// baseline (speedup 1.0000x reference)
#include <cuda_runtime.h>
#include <math.h>

#define EMB   512
#define HDIM  512
#define SEQ   2048
#define NENT  256
#define KTOK  8
#define G4H   2048   // 4*HDIM

#define NCTA  64     // CTAs per direction in the recurrence kernel
#define JPC   8      // h-indices owned per CTA (NCTA*JPC == HDIM)

// ---------------- scratch (device globals; no allocation allowed) ----------
__device__ float g_xproj[2][SEQ][G4H];   // 32 MB: x @ W_ih.T + b, both dirs
__device__ float g_h[2][SEQ][HDIM];      // 8 MB: full hidden history (also the broadcast buffer)
__device__ int   g_flags[2 * NCTA];      // step-completion flags

// ===========================================================================
// Kernel 1: fused embedding gather + x_proj GEMM (+bias), both directions.
//   out[d][t][r] = b_d[r] + sum_e emb_table[token_ids[t]][e] * W_ih_d[r][e]
// 64x64 output tile per CTA, K-chunks of 16, smem-tiled fp32.
// ===========================================================================
__global__ __launch_bounds__(256) void xproj_kernel(
    const float* __restrict__ emb_table,
    const int*   __restrict__ token_ids,
    const float* __restrict__ W_ih_f, const float* __restrict__ b_f,
    const float* __restrict__ W_ih_b, const float* __restrict__ b_b)
{
    __shared__ int   tok[64];
    __shared__ float As[16][68];   // [e_local][t_local], padded (68*4B, 16B-aligned rows)
    __shared__ float Bs[16][68];   // [e_local][r_local]

    const int tid = threadIdx.x;
    const int t0  = blockIdx.x * 64;
    const int r0  = blockIdx.y * 64;
    const int d   = blockIdx.z;

    // reset recurrence flags once per launch (any single block; all GEMM blocks
    // finish before the recurrence kernel starts -> no race)
    if (blockIdx.x == 0 && blockIdx.y == 0 && blockIdx.z == 0 && tid < 2 * NCTA)
        g_flags[tid] = 0;

    if (tid < 64) tok[tid] = token_ids[t0 + tid];
    __syncthreads();

    const float* __restrict__ Wih  = d ? W_ih_b : W_ih_f;
    const float* __restrict__ bias = d ? b_b    : b_f;

    float acc[4][4];
    #pragma unroll
    for (int i = 0; i < 4; i++)
        #pragma unroll
        for (int j = 0; j < 4; j++) acc[i][j] = 0.f;

    const int lrow = tid >> 2;            // 0..63 (row within tile for loads)
    const int e4   = tid & 3;             // which float4 of the 16-wide K chunk
    const int tx   = tid & 15;            // t micro-tile index (compute)
    const int ty   = tid >> 4;            // r micro-tile index (compute)

    const size_t arow = (size_t)tok[lrow] * EMB;
    const size_t brow = (size_t)(r0 + lrow) * EMB;

    for (int k0 = 0; k0 < EMB; k0 += 16) {
        float4 av = *(const float4*)(emb_table + arow + k0 + e4 * 4);
        float4 bv = *(const float4*)(Wih       + brow + k0 + e4 * 4);
        __syncthreads();   // previous chunk fully consumed
        As[e4 * 4 + 0][lrow] = av.x; As[e4 * 4 + 1][lrow] = av.y;
        As[e4 * 4 + 2][lrow] = av.z; As[e4 * 4 + 3][lrow] = av.w;
        Bs[e4 * 4 + 0][lrow] = bv.x; Bs[e4 * 4 + 1][lrow] = bv.y;
        Bs[e4 * 4 + 2][lrow] = bv.z; Bs[e4 * 4 + 3][lrow] = bv.w;
        __syncthreads();
        #pragma unroll
        for (int kk = 0; kk < 16; kk++) {
            float4 a = *(const float4*)&As[kk][tx * 4];
            float4 b = *(const float4*)&Bs[kk][ty * 4];
            acc[0][0] = fmaf(a.x, b.x, acc[0][0]); acc[0][1] = fmaf(a.x, b.y, acc[0][1]);
            acc[0][2] = fmaf(a.x, b.z, acc[0][2]); acc[0][3] = fmaf(a.x, b.w, acc[0][3]);
            acc[1][0] = fmaf(a.y, b.x, acc[1][0]); acc[1][1] = fmaf(a.y, b.y, acc[1][1]);
            acc[1][2] = fmaf(a.y, b.z, acc[1][2]); acc[1][3] = fmaf(a.y, b.w, acc[1][3]);
            acc[2][0] = fmaf(a.z, b.x, acc[2][0]); acc[2][1] = fmaf(a.z, b.y, acc[2][1]);
            acc[2][2] = fmaf(a.z, b.z, acc[2][2]); acc[2][3] = fmaf(a.z, b.w, acc[2][3]);
            acc[3][0] = fmaf(a.w, b.x, acc[3][0]); acc[3][1] = fmaf(a.w, b.y, acc[3][1]);
            acc[3][2] = fmaf(a.w, b.z, acc[3][2]); acc[3][3] = fmaf(a.w, b.w, acc[3][3]);
        }
    }

    float4 b4 = *(const float4*)(bias + r0 + ty * 4);
    #pragma unroll
    for (int i = 0; i < 4; i++) {
        int t = t0 + tx * 4 + i;
        float4 o = make_float4(acc[i][0] + b4.x, acc[i][1] + b4.y,
                               acc[i][2] + b4.z, acc[i][3] + b4.w);
        *(float4*)&g_xproj[d][t][r0 + ty * 4] = o;
    }
}

// ===========================================================================
// Kernel 2: persistent bi-LSTM recurrence.
// Grid = 128 CTAs (64 per direction), 256 threads each; all co-resident on
// one wave (<=148 SMs), so custom flag sync cannot deadlock.
// CTA `cb` in direction `d` owns h-indices j in [cb*8, cb*8+8): its 32
// W_hh rows (4 gates x 8 j) live in REGISTERS (64 floats/thread).
// Per step: local 32x512 GEMV slice -> 8-lane shuffle reduce -> gate math on
// threads 0..7 -> publish h slice to g_h (history == broadcast buffer) ->
// release flag; consumers acquire all 64 flags, then read full h[512].
// ===========================================================================
__global__ __launch_bounds__(256) void lstm_kernel(
    const float* __restrict__ W_hh_f,
    const float* __restrict__ W_hh_b)
{
    const int tid = threadIdx.x;
    const int bx  = blockIdx.x;
    const int d   = bx >> 6;        // direction: 0 fwd, 1 bwd
    const int cb  = bx & 63;        // CTA index within direction
    const int j0  = cb * JPC;

    const float* __restrict__ Whh = d ? W_hh_b : W_hh_f;

    const int r  = tid >> 3;        // local row 0..31  (= gate*8 + jj)
    const int cg = tid & 7;         // column group (64 cols each)
    const int q  = r >> 3;          // gate 0..3 (i,f,g,o)
    const int jj = r & 7;
    const int grow = q * HDIM + j0 + jj;   // global W_hh row

    // stage this thread's 64 weights into registers
    const float4* wp = (const float4*)(Whh + (size_t)grow * HDIM + cg * 64);
    float4 w[16];
    #pragma unroll
    for (int i = 0; i < 16; i++) w[i] = wp[i];

    __shared__ float hsm[HDIM];
    __shared__ float gacc[32];

    float c = 0.f;                  // cell state (threads 0..7 only)
    int* myflags = g_flags + d * NCTA;

    #pragma unroll 1
    for (int step = 0; step < SEQ; step++) {
        const int t = d ? (SEQ - 1 - step) : step;

        // prefetch x_proj gate values early (independent of h)
        float xp0 = 0.f, xp1 = 0.f, xp2 = 0.f, xp3 = 0.f;
        if (tid < 8) {
            const float* xr = &g_xproj[d][t][0];
            xp0 = __ldg(xr + 0 * HDIM + j0 + tid);
            xp1 = __ldg(xr + 1 * HDIM + j0 + tid);
            xp2 = __ldg(xr + 2 * HDIM + j0 + tid);
            xp3 = __ldg(xr + 3 * HDIM + j0 + tid);
        }

        if (step == 0) {
            if (tid < 128) ((float4*)hsm)[tid] = make_float4(0.f, 0.f, 0.f, 0.f);
        } else {
            if (tid < NCTA) {   // wait until every CTA of this dir finished step-1
                int v;
                do {
                    asm volatile("ld.global.acquire.gpu.b32 %0, [%1];"
                                 : "=r"(v) : "l"(myflags + tid) : "memory");
                } while (v < step);
            }
            __syncthreads();
            const int tprev = d ? (t + 1) : (t - 1);
            if (tid < 128)
                ((float4*)hsm)[tid] = ((const float4*)&g_h[d][tprev][0])[tid];
        }
        __syncthreads();

        // local GEMV slice: row r, cols [cg*64, cg*64+64)
        float a = 0.f;
        const float4* h4 = (const float4*)(hsm + cg * 64);
        #pragma unroll
        for (int i = 0; i < 16; i++) {
            float4 hv = h4[i];
            a = fmaf(w[i].x, hv.x, a);
            a = fmaf(w[i].y, hv.y, a);
            a = fmaf(w[i].z, hv.z, a);
            a = fmaf(w[i].w, hv.w, a);
        }
        // reduce across the 8 column groups (aligned 8-lane subsets of a warp)
        a += __shfl_xor_sync(0xffffffffu, a, 4);
        a += __shfl_xor_sync(0xffffffffu, a, 2);
        a += __shfl_xor_sync(0xffffffffu, a, 1);
        if (cg == 0) gacc[r] = a;
        __syncthreads();

        // gate math + publish h slice (threads 0..7, thread jj owns c[jj])
        if (tid < 8) {
            float gi = xp0 + gacc[0 * 8 + tid];
            float gf = xp1 + gacc[1 * 8 + tid];
            float gg = xp2 + gacc[2 * 8 + tid];
            float go = xp3 + gacc[3 * 8 + tid];
            float ig = 1.f / (1.f + expf(-gi));
            float fg = 1.f / (1.f + expf(-gf));
            float og = 1.f / (1.f + expf(-go));
            c = fg * c + ig * tanhf(gg);
            float hv = og * tanhf(c);
            g_h[d][t][j0 + tid] = hv;
        }
        __syncthreads();   // h-slice stores ordered before thread 0's release
        if (tid == 0) {
            asm volatile("st.global.release.gpu.b32 [%0], %1;"
                         :: "l"(myflags + cb), "r"(step + 1) : "memory");
        }
    }
}

// ===========================================================================
// Kernel 3: per-entity attention pool. entity_seg == repeat(arange(256), 8),
// so entity e owns entries [8e, 8e+8). One 256-thread CTA per entity.
// ===========================================================================
__global__ __launch_bounds__(256) void entity_kernel(
    const float* __restrict__ w_attn,
    const float* __restrict__ b_attn,
    const int*   __restrict__ entity_pos,
    float*       __restrict__ out)
{
    __shared__ int   pos[8];
    __shared__ float ssm[8];
    __shared__ float wsm[8];

    const int e   = blockIdx.x;
    const int tid = threadIdx.x;

    if (tid < 8) pos[tid] = entity_pos[e * KTOK + tid];
    __syncthreads();

    // scores: warp k computes dot(blstm[pos[k]], w_attn) + b_attn
    const int warp = tid >> 5, lane = tid & 31;
    const int p = pos[warp];
    float a = 0.f;
    for (int cc = lane; cc < HDIM; cc += 32)
        a = fmaf(g_h[0][p][cc], w_attn[cc], a);
    for (int cc = lane; cc < HDIM; cc += 32)
        a = fmaf(g_h[1][p][cc], w_attn[HDIM + cc], a);
    #pragma unroll
    for (int o = 16; o > 0; o >>= 1) a += __shfl_xor_sync(0xffffffffu, a, o);
    if (lane == 0) ssm[warp] = a + b_attn[0];
    __syncthreads();

    if (tid == 0) {
        float m = ssm[0];
        #pragma unroll
        for (int k = 1; k < 8; k++) m = fmaxf(m, ssm[k]);
        float ex[8], den = 0.f;
        #pragma unroll
        for (int k = 0; k < 8; k++) { ex[k] = expf(ssm[k] - m); den += ex[k]; }
        #pragma unroll
        for (int k = 0; k < 8; k++) wsm[k] = ex[k] / den;
    }
    __syncthreads();

    // weighted sum: threads 0..127 cover fwd half, 128..255 bwd half (float4)
    const int half = tid >> 7;
    const int c4   = tid & 127;
    float4 acc = make_float4(0.f, 0.f, 0.f, 0.f);
    #pragma unroll
    for (int k = 0; k < 8; k++) {
        float wk = wsm[k];
        float4 v = ((const float4*)&g_h[half][pos[k]][0])[c4];
        acc.x = fmaf(wk, v.x, acc.x);
        acc.y = fmaf(wk, v.y, acc.y);
        acc.z = fmaf(wk, v.z, acc.z);
        acc.w = fmaf(wk, v.w, acc.w);
    }
    ((float4*)(out + (size_t)e * (2 * HDIM) + half * HDIM))[c4] = acc;
}

// ===========================================================================
extern "C" void kernel_launch(void* const* d_in, const int* in_sizes, int n_in,
                              void* d_out, int out_size)
{
    const float* emb_table  = (const float*)d_in[0];
    const float* W_ih_f     = (const float*)d_in[1];
    const float* W_hh_f     = (const float*)d_in[2];
    const float* b_f        = (const float*)d_in[3];
    const float* W_ih_b     = (const float*)d_in[4];
    const float* W_hh_b     = (const float*)d_in[5];
    const float* b_b        = (const float*)d_in[6];
    const float* w_attn     = (const float*)d_in[7];
    const float* b_attn     = (const float*)d_in[8];
    const int*   token_ids  = (const int*)d_in[9];
    const int*   entity_pos = (const int*)d_in[10];
    // d_in[11] entity_seg: structure is repeat(arange(NENT), KTOK) -> implicit

    xproj_kernel<<<dim3(32, 32, 2), 256>>>(emb_table, token_ids,
                                           W_ih_f, b_f, W_ih_b, b_b);
    lstm_kernel<<<2 * NCTA, 256>>>(W_hh_f, W_hh_b);
    entity_kernel<<<NENT, 256>>>(w_attn, b_attn, entity_pos, (float*)d_out);
}

// round 2
// speedup vs baseline: 1.8144x; 1.8144x over previous
#include <cuda_runtime.h>
#include <math.h>

#define EMB   512
#define HDIM  512
#define SEQ   2048
#define NENT  256
#define KTOK  8
#define G4H   2048   // 4*HDIM

#define NCTA  64     // CTAs per direction in the recurrence kernel
#define JPC   8      // h-indices owned per CTA (NCTA*JPC == HDIM)

// ---------------- scratch (device globals; no allocation allowed) ----------
__device__ float g_xproj[2][SEQ][G4H];        // 32 MB: x @ W_ih.T + b, both dirs
__device__ float g_h[2][SEQ][HDIM];           // 8 MB: hidden history == broadcast buffer
__device__ __align__(128) int g_cnt[2][32];   // per-direction monotonic arrival counter (own line)

// fast saturating activations (MUFU EX2 based); safe at +/-inf
__device__ __forceinline__ float fast_sigmoid(float x) {
    return __fdividef(1.f, 1.f + __expf(-x));
}
__device__ __forceinline__ float fast_tanh(float x) {
    return __fdividef(2.f, 1.f + __expf(-2.f * x)) - 1.f;
}

// ===========================================================================
// Kernel 1: fused embedding gather + x_proj GEMM (+bias), both directions.
//   out[d][t][r] = b_d[r] + sum_e emb_table[token_ids[t]][e] * W_ih_d[r][e]
// ===========================================================================
__global__ __launch_bounds__(256) void xproj_kernel(
    const float* __restrict__ emb_table,
    const int*   __restrict__ token_ids,
    const float* __restrict__ W_ih_f, const float* __restrict__ b_f,
    const float* __restrict__ W_ih_b, const float* __restrict__ b_b)
{
    __shared__ int   tok[64];
    __shared__ float As[16][68];   // [e_local][t_local]
    __shared__ float Bs[16][68];   // [e_local][r_local]

    const int tid = threadIdx.x;
    const int t0  = blockIdx.x * 64;
    const int r0  = blockIdx.y * 64;
    const int d   = blockIdx.z;

    // reset recurrence counters once per launch (stream order: all xproj blocks
    // retire before lstm_kernel starts)
    if (blockIdx.x == 0 && blockIdx.y == 0 && blockIdx.z == 0 && tid < 2)
        g_cnt[tid][0] = 0;

    if (tid < 64) tok[tid] = token_ids[t0 + tid];
    __syncthreads();

    const float* __restrict__ Wih  = d ? W_ih_b : W_ih_f;
    const float* __restrict__ bias = d ? b_b    : b_f;

    float acc[4][4];
    #pragma unroll
    for (int i = 0; i < 4; i++)
        #pragma unroll
        for (int j = 0; j < 4; j++) acc[i][j] = 0.f;

    const int lrow = tid >> 2;
    const int e4   = tid & 3;
    const int tx   = tid & 15;
    const int ty   = tid >> 4;

    const size_t arow = (size_t)tok[lrow] * EMB;
    const size_t brow = (size_t)(r0 + lrow) * EMB;

    for (int k0 = 0; k0 < EMB; k0 += 16) {
        float4 av = *(const float4*)(emb_table + arow + k0 + e4 * 4);
        float4 bv = *(const float4*)(Wih       + brow + k0 + e4 * 4);
        __syncthreads();
        As[e4 * 4 + 0][lrow] = av.x; As[e4 * 4 + 1][lrow] = av.y;
        As[e4 * 4 + 2][lrow] = av.z; As[e4 * 4 + 3][lrow] = av.w;
        Bs[e4 * 4 + 0][lrow] = bv.x; Bs[e4 * 4 + 1][lrow] = bv.y;
        Bs[e4 * 4 + 2][lrow] = bv.z; Bs[e4 * 4 + 3][lrow] = bv.w;
        __syncthreads();
        #pragma unroll
        for (int kk = 0; kk < 16; kk++) {
            float4 a = *(const float4*)&As[kk][tx * 4];
            float4 b = *(const float4*)&Bs[kk][ty * 4];
            acc[0][0] = fmaf(a.x, b.x, acc[0][0]); acc[0][1] = fmaf(a.x, b.y, acc[0][1]);
            acc[0][2] = fmaf(a.x, b.z, acc[0][2]); acc[0][3] = fmaf(a.x, b.w, acc[0][3]);
            acc[1][0] = fmaf(a.y, b.x, acc[1][0]); acc[1][1] = fmaf(a.y, b.y, acc[1][1]);
            acc[1][2] = fmaf(a.y, b.z, acc[1][2]); acc[1][3] = fmaf(a.y, b.w, acc[1][3]);
            acc[2][0] = fmaf(a.z, b.x, acc[2][0]); acc[2][1] = fmaf(a.z, b.y, acc[2][1]);
            acc[2][2] = fmaf(a.z, b.z, acc[2][2]); acc[2][3] = fmaf(a.z, b.w, acc[2][3]);
            acc[3][0] = fmaf(a.w, b.x, acc[3][0]); acc[3][1] = fmaf(a.w, b.y, acc[3][1]);
            acc[3][2] = fmaf(a.w, b.z, acc[3][2]); acc[3][3] = fmaf(a.w, b.w, acc[3][3]);
        }
    }

    float4 b4 = *(const float4*)(bias + r0 + ty * 4);
    #pragma unroll
    for (int i = 0; i < 4; i++) {
        int t = t0 + tx * 4 + i;
        float4 o = make_float4(acc[i][0] + b4.x, acc[i][1] + b4.y,
                               acc[i][2] + b4.z, acc[i][3] + b4.w);
        *(float4*)&g_xproj[d][t][r0 + ty * 4] = o;
    }
}

// ===========================================================================
// Kernel 2: persistent bi-LSTM recurrence, 128 co-resident CTAs.
// Sync: one monotonic arrival counter per direction; each CTA red.add.release
// +1 after publishing its h slice; one thread per CTA acquire-polls cnt>=64*step.
// ===========================================================================
__global__ __launch_bounds__(256) void lstm_kernel(
    const float* __restrict__ W_hh_f,
    const float* __restrict__ W_hh_b)
{
    const int tid = threadIdx.x;
    const int bx  = blockIdx.x;
    const int d   = bx >> 6;        // direction
    const int cb  = bx & 63;        // CTA index within direction
    const int j0  = cb * JPC;

    const float* __restrict__ Whh = d ? W_hh_b : W_hh_f;

    const int r  = tid >> 3;        // local row 0..31 (= gate*8 + jj)
    const int cg = tid & 7;         // column group (64 cols each)
    const int q  = r >> 3;          // gate 0..3 (i,f,g,o)
    const int jj = r & 7;
    const int grow = q * HDIM + j0 + jj;

    // stage this thread's 64 weights into registers
    const float4* wp = (const float4*)(Whh + (size_t)grow * HDIM + cg * 64);
    float4 w[16];
    #pragma unroll
    for (int i = 0; i < 16; i++) w[i] = wp[i];

    __shared__ float hsm[HDIM];
    __shared__ float gacc[32];

    float c = 0.f;
    int* cnt = &g_cnt[d][0];

    #pragma unroll 1
    for (int step = 0; step < SEQ; step++) {
        const int t = d ? (SEQ - 1 - step) : step;

        // issue x_proj gate loads early; their latency hides under the wait
        float xp0 = 0.f, xp1 = 0.f, xp2 = 0.f, xp3 = 0.f;
        if (tid < 8) {
            const float* xr = &g_xproj[d][t][0];
            xp0 = __ldg(xr + 0 * HDIM + j0 + tid);
            xp1 = __ldg(xr + 1 * HDIM + j0 + tid);
            xp2 = __ldg(xr + 2 * HDIM + j0 + tid);
            xp3 = __ldg(xr + 3 * HDIM + j0 + tid);
        }

        if (step > 0 && tid == 0) {
            const int target = step * NCTA;
            int v;
            do {
                asm volatile("ld.global.acquire.gpu.b32 %0, [%1];"
                             : "=r"(v) : "l"(cnt) : "memory");
            } while (v < target);
        }
        __syncthreads();   // B1: wait done; previous-iter hsm/gacc consumers done

        if (step == 0) {
            if (tid < 128) ((float4*)hsm)[tid] = make_float4(0.f, 0.f, 0.f, 0.f);
        } else {
            const int tprev = d ? (t + 1) : (t - 1);
            if (tid < 128)
                ((float4*)hsm)[tid] = ((const float4*)&g_h[d][tprev][0])[tid];
        }
        __syncthreads();   // B2: hsm ready

        // local GEMV slice: row r, cols [cg*64, cg*64+64)
        float a = 0.f;
        const float4* h4 = (const float4*)(hsm + cg * 64);
        #pragma unroll
        for (int i = 0; i < 16; i++) {
            float4 hv = h4[i];
            a = fmaf(w[i].x, hv.x, a);
            a = fmaf(w[i].y, hv.y, a);
            a = fmaf(w[i].z, hv.z, a);
            a = fmaf(w[i].w, hv.w, a);
        }
        a += __shfl_xor_sync(0xffffffffu, a, 4);
        a += __shfl_xor_sync(0xffffffffu, a, 2);
        a += __shfl_xor_sync(0xffffffffu, a, 1);
        if (cg == 0) gacc[r] = a;
        __syncthreads();   // B3: gacc ready

        if (tid < 8) {
            float gi = xp0 + gacc[0 * 8 + tid];
            float gf = xp1 + gacc[1 * 8 + tid];
            float gg = xp2 + gacc[2 * 8 + tid];
            float go = xp3 + gacc[3 * 8 + tid];
            float ig = fast_sigmoid(gi);
            float fg = fast_sigmoid(gf);
            float og = fast_sigmoid(go);
            c = fg * c + ig * fast_tanh(gg);
            float hv = og * fast_tanh(c);
            g_h[d][t][j0 + tid] = hv;    // one 32B sector per CTA
        }
        __syncthreads();   // B4: h stores ordered before the release-add
        if (tid == 0) {
            asm volatile("red.add.release.gpu.global.s32 [%0], %1;"
                         :: "l"(cnt), "r"(1) : "memory");
        }
    }
}

// ===========================================================================
// Kernel 3: per-entity attention pool (entity_seg == repeat(arange(256), 8)).
// ===========================================================================
__global__ __launch_bounds__(256) void entity_kernel(
    const float* __restrict__ w_attn,
    const float* __restrict__ b_attn,
    const int*   __restrict__ entity_pos,
    float*       __restrict__ out)
{
    __shared__ int   pos[8];
    __shared__ float ssm[8];
    __shared__ float wsm[8];

    const int e   = blockIdx.x;
    const int tid = threadIdx.x;

    if (tid < 8) pos[tid] = entity_pos[e * KTOK + tid];
    __syncthreads();

    const int warp = tid >> 5, lane = tid & 31;
    const int p = pos[warp];
    float a = 0.f;
    for (int cc = lane; cc < HDIM; cc += 32)
        a = fmaf(g_h[0][p][cc], w_attn[cc], a);
    for (int cc = lane; cc < HDIM; cc += 32)
        a = fmaf(g_h[1][p][cc], w_attn[HDIM + cc], a);
    #pragma unroll
    for (int o = 16; o > 0; o >>= 1) a += __shfl_xor_sync(0xffffffffu, a, o);
    if (lane == 0) ssm[warp] = a + b_attn[0];
    __syncthreads();

    if (tid == 0) {
        float m = ssm[0];
        #pragma unroll
        for (int k = 1; k < 8; k++) m = fmaxf(m, ssm[k]);
        float ex[8], den = 0.f;
        #pragma unroll
        for (int k = 0; k < 8; k++) { ex[k] = expf(ssm[k] - m); den += ex[k]; }
        #pragma unroll
        for (int k = 0; k < 8; k++) wsm[k] = ex[k] / den;
    }
    __syncthreads();

    const int half = tid >> 7;
    const int c4   = tid & 127;
    float4 acc = make_float4(0.f, 0.f, 0.f, 0.f);
    #pragma unroll
    for (int k = 0; k < 8; k++) {
        float wk = wsm[k];
        float4 v = ((const float4*)&g_h[half][pos[k]][0])[c4];
        acc.x = fmaf(wk, v.x, acc.x);
        acc.y = fmaf(wk, v.y, acc.y);
        acc.z = fmaf(wk, v.z, acc.z);
        acc.w = fmaf(wk, v.w, acc.w);
    }
    ((float4*)(out + (size_t)e * (2 * HDIM) + half * HDIM))[c4] = acc;
}

// ===========================================================================
extern "C" void kernel_launch(void* const* d_in, const int* in_sizes, int n_in,
                              void* d_out, int out_size)
{
    const float* emb_table  = (const float*)d_in[0];
    const float* W_ih_f     = (const float*)d_in[1];
    const float* W_hh_f     = (const float*)d_in[2];
    const float* b_f        = (const float*)d_in[3];
    const float* W_ih_b     = (const float*)d_in[4];
    const float* W_hh_b     = (const float*)d_in[5];
    const float* b_b        = (const float*)d_in[6];
    const float* w_attn     = (const float*)d_in[7];
    const float* b_attn     = (const float*)d_in[8];
    const int*   token_ids  = (const int*)d_in[9];
    const int*   entity_pos = (const int*)d_in[10];
    // d_in[11] entity_seg: repeat(arange(NENT), KTOK) -> implicit

    xproj_kernel<<<dim3(32, 32, 2), 256>>>(emb_table, token_ids,
                                           W_ih_f, b_f, W_ih_b, b_b);
    lstm_kernel<<<2 * NCTA, 256>>>(W_hh_f, W_hh_b);
    entity_kernel<<<NENT, 256>>>(w_attn, b_attn, entity_pos, (float*)d_out);
}